// round 1
// baseline (speedup 1.0000x reference)
#include <cuda_runtime.h>

#define NB 16
#define HWPIX (768*768)          // 589824 pixels per batch
#define NUM_IDS 128
#define NVEC (HWPIX/4)           // 147456 float4/int4 per batch-plane

// ---- scratch (allocation-free: __device__ globals) ----
__device__ int   g_counts[NB * NUM_IDS];
__device__ float g_invnorm[NB * NUM_IDS];
__device__ float g_acc[2 * NB];          // [0..15]=sin sums, [16..31]=cos sums

// ---------------------------------------------------------------------------
// K0: zero scratch (runs every launch so graph replays are deterministic)
// ---------------------------------------------------------------------------
__global__ void k_zero() {
    int i = blockIdx.x * blockDim.x + threadIdx.x;
    if (i < NB * NUM_IDS) g_counts[i] = 0;
    if (i < 2 * NB)       g_acc[i] = 0.0f;
}

// ---------------------------------------------------------------------------
// K1: per-batch 128-bin histogram of instance ids (shared-mem privatized)
// grid = (blocks_per_batch, NB)
// ---------------------------------------------------------------------------
__global__ void k_hist(const int* __restrict__ inst) {
    __shared__ int sh[NUM_IDS];
    const int b = blockIdx.y;
    for (int i = threadIdx.x; i < NUM_IDS; i += blockDim.x) sh[i] = 0;
    __syncthreads();

    const int4* p = (const int4*)(inst + (size_t)b * HWPIX);
    for (int i = blockIdx.x * blockDim.x + threadIdx.x; i < NVEC;
         i += gridDim.x * blockDim.x) {
        int4 v = p[i];
        atomicAdd(&sh[v.x], 1);
        atomicAdd(&sh[v.y], 1);
        atomicAdd(&sh[v.z], 1);
        atomicAdd(&sh[v.w], 1);
    }
    __syncthreads();
    for (int i = threadIdx.x; i < NUM_IDS; i += blockDim.x)
        if (sh[i]) atomicAdd(&g_counts[b * NUM_IDS + i], sh[i]);
}

// ---------------------------------------------------------------------------
// K2: single block — compute num_instances, num_bg_pixels, then the
// per-(batch,id) inverse-norm table.
// ---------------------------------------------------------------------------
__global__ void k_norm() {
    const int tid = threadIdx.x;           // 256 threads
    __shared__ int sni[256];
    __shared__ int snbg[256];

    int ni = 0, nbg = 0;
    for (int i = tid; i < NB * NUM_IDS; i += 256) {
        int c  = g_counts[i];
        int id = i & (NUM_IDS - 1);
        if (id == 0) nbg += c;
        else         ni  += (c > 0);
    }
    sni[tid] = ni; snbg[tid] = nbg;
    __syncthreads();
    for (int s = 128; s > 0; s >>= 1) {
        if (tid < s) { sni[tid] += sni[tid + s]; snbg[tid] += snbg[tid + s]; }
        __syncthreads();
    }
    __shared__ float inv_bg, two_ni;
    if (tid == 0) {
        inv_bg = 1.0f / (2.0f * (float)snbg[0]);
        two_ni = 2.0f * (float)sni[0];
    }
    __syncthreads();

    for (int i = tid; i < NB * NUM_IDS; i += 256) {
        int id = i & (NUM_IDS - 1);
        float c = (float)max(g_counts[i], 1);
        g_invnorm[i] = (id == 0) ? inv_bg : 1.0f / (c * two_ni);
    }
}

// ---------------------------------------------------------------------------
// K3: fused weighted-L1 reduction.
// grid = (blocks_per_batch, NB); block = 256.
// Reads: inst (int4), pred ch0/ch1 (float4), gt ch2/ch3 (float4).
// Per-thread register accumulation -> warp shfl reduce -> block reduce ->
// one atomicAdd per block per accumulator.
// ---------------------------------------------------------------------------
__global__ void k_loss(const float* __restrict__ pred,
                       const int*   __restrict__ inst,
                       const float* __restrict__ gt) {
    const int b = blockIdx.y;
    __shared__ float s_inv[NUM_IDS];
    for (int i = threadIdx.x; i < NUM_IDS; i += blockDim.x)
        s_inv[i] = g_invnorm[b * NUM_IDS + i];
    __syncthreads();

    const float4* ps = (const float4*)(pred + (size_t)b * 2 * HWPIX);
    const float4* pc = (const float4*)(pred + (size_t)b * 2 * HWPIX + HWPIX);
    const float4* gs = (const float4*)(gt   + (size_t)b * 5 * HWPIX + 2 * (size_t)HWPIX);
    const float4* gc = (const float4*)(gt   + (size_t)b * 5 * HWPIX + 3 * (size_t)HWPIX);
    const int4*   pi = (const int4*)(inst + (size_t)b * HWPIX);

    float asin_ = 0.0f, acos_ = 0.0f;
    for (int i = blockIdx.x * blockDim.x + threadIdx.x; i < NVEC;
         i += gridDim.x * blockDim.x) {
        int4   id = pi[i];
        float4 s  = ps[i];
        float4 c  = pc[i];
        float4 g1 = gs[i];
        float4 g2 = gc[i];
        float w0 = s_inv[id.x], w1 = s_inv[id.y], w2 = s_inv[id.z], w3 = s_inv[id.w];
        asin_ += w0 * fabsf(s.x - g1.x) + w1 * fabsf(s.y - g1.y)
               + w2 * fabsf(s.z - g1.z) + w3 * fabsf(s.w - g1.w);
        acos_ += w0 * fabsf(c.x - g2.x) + w1 * fabsf(c.y - g2.y)
               + w2 * fabsf(c.z - g2.z) + w3 * fabsf(c.w - g2.w);
    }

    // warp reduce
    for (int off = 16; off > 0; off >>= 1) {
        asin_ += __shfl_down_sync(0xFFFFFFFFu, asin_, off);
        acos_ += __shfl_down_sync(0xFFFFFFFFu, acos_, off);
    }
    __shared__ float ws[8], wc[8];
    int lane = threadIdx.x & 31, warp = threadIdx.x >> 5;
    if (lane == 0) { ws[warp] = asin_; wc[warp] = acos_; }
    __syncthreads();
    if (warp == 0) {
        float vs = (lane < 8) ? ws[lane] : 0.0f;
        float vc = (lane < 8) ? wc[lane] : 0.0f;
        for (int off = 4; off > 0; off >>= 1) {
            vs += __shfl_down_sync(0xFFFFFFFFu, vs, off);
            vc += __shfl_down_sync(0xFFFFFFFFu, vc, off);
        }
        if (lane == 0) {
            atomicAdd(&g_acc[b], vs);
            atomicAdd(&g_acc[NB + b], vc);
        }
    }
}

// ---------------------------------------------------------------------------
// K4: write the 5x16 output tuple (loss, dir_total, centers, sin, cos)
// ---------------------------------------------------------------------------
__global__ void k_out(float* __restrict__ out) {
    int b = threadIdx.x;
    if (b < NB) {
        float s = g_acc[b];
        float c = g_acc[NB + b];
        float t = s + c;
        out[0 * NB + b] = t;     // loss
        out[1 * NB + b] = t;     // loss_direction_total
        out[2 * NB + b] = 0.0f;  // loss_centers
        out[3 * NB + b] = s;     // loss_sin
        out[4 * NB + b] = c;     // loss_cos
    }
}

extern "C" void kernel_launch(void* const* d_in, const int* in_sizes, int n_in,
                              void* d_out, int out_size) {
    const float* pred = (const float*)d_in[0];   // (16,2,768,768) f32
    const int*   inst = (const int*)d_in[1];     // (16,768,768) i32
    // d_in[2] = labels (unused: W_FG == W_BG == 1 and labels==0 <=> inst==0)
    const float* gt   = (const float*)d_in[3];   // (16,5,768,768) f32
    float* out = (float*)d_out;                  // 80 f32

    k_zero<<<8, 256>>>();
    k_hist<<<dim3(36, NB), 256>>>(inst);
    k_norm<<<1, 256>>>();
    k_loss<<<dim3(48, NB), 256>>>(pred, inst, gt);
    k_out<<<1, 32>>>(out);
}